// round 1
// baseline (speedup 1.0000x reference)
#include <cuda_runtime.h>
#include <cuda_bf16.h>

// Scratch accumulators: [0] = sum(bce*m), [1] = sum(m)
__device__ double g_acc[2];

__global__ void init_acc_kernel() {
    g_acc[0] = 0.0;
    g_acc[1] = 0.0;
}

__global__ __launch_bounds__(256) void loss_kernel(
    const float4* __restrict__ x4,
    const float*  __restrict__ label,
    const float4* __restrict__ pm4,
    const float4* __restrict__ nm4,
    int n4, int hw4)
{
    float s_bce = 0.0f;
    float s_cnt = 0.0f;

    int stride = gridDim.x * blockDim.x;
    for (int i = blockIdx.x * blockDim.x + threadIdx.x; i < n4; i += stride) {
        float4 xv = x4[i];
        float4 pv = pm4[i];
        float4 nv = nm4[i];
        float y = __ldg(&label[i / hw4]);   // constant within the float4

        // lane 0
        {
            float x = xv.x;
            float m = (pv.x > 0.5f && nv.x > 0.5f) ? 1.0f : 0.0f;
            float bce = fmaxf(x, 0.0f) - x * y + log1pf(__expf(-fabsf(x)));
            s_bce += bce * m;
            s_cnt += m;
        }
        {
            float x = xv.y;
            float m = (pv.y > 0.5f && nv.y > 0.5f) ? 1.0f : 0.0f;
            float bce = fmaxf(x, 0.0f) - x * y + log1pf(__expf(-fabsf(x)));
            s_bce += bce * m;
            s_cnt += m;
        }
        {
            float x = xv.z;
            float m = (pv.z > 0.5f && nv.z > 0.5f) ? 1.0f : 0.0f;
            float bce = fmaxf(x, 0.0f) - x * y + log1pf(__expf(-fabsf(x)));
            s_bce += bce * m;
            s_cnt += m;
        }
        {
            float x = xv.w;
            float m = (pv.w > 0.5f && nv.w > 0.5f) ? 1.0f : 0.0f;
            float bce = fmaxf(x, 0.0f) - x * y + log1pf(__expf(-fabsf(x)));
            s_bce += bce * m;
            s_cnt += m;
        }
    }

    // Warp reduction
    #pragma unroll
    for (int off = 16; off > 0; off >>= 1) {
        s_bce += __shfl_down_sync(0xFFFFFFFFu, s_bce, off);
        s_cnt += __shfl_down_sync(0xFFFFFFFFu, s_cnt, off);
    }

    // Block reduction via shared memory
    __shared__ float sh_bce[8];
    __shared__ float sh_cnt[8];
    int wid = threadIdx.x >> 5;
    int lid = threadIdx.x & 31;
    if (lid == 0) {
        sh_bce[wid] = s_bce;
        sh_cnt[wid] = s_cnt;
    }
    __syncthreads();
    if (wid == 0) {
        int nw = blockDim.x >> 5;
        float b = (lid < nw) ? sh_bce[lid] : 0.0f;
        float c = (lid < nw) ? sh_cnt[lid] : 0.0f;
        #pragma unroll
        for (int off = 4; off > 0; off >>= 1) {
            b += __shfl_down_sync(0xFFFFFFFFu, b, off);
            c += __shfl_down_sync(0xFFFFFFFFu, c, off);
        }
        if (lid == 0) {
            atomicAdd(&g_acc[0], (double)b);
            atomicAdd(&g_acc[1], (double)c);
        }
    }
}

__global__ void finalize_kernel(float* __restrict__ out) {
    double cnt = g_acc[1];
    if (cnt < 1.0) cnt = 1.0;
    out[0] = (float)(g_acc[0] / cnt);
}

extern "C" void kernel_launch(void* const* d_in, const int* in_sizes, int n_in,
                              void* d_out, int out_size) {
    const float* x  = (const float*)d_in[0];  // cancer_logits (B,1,H,W)
    const float* y  = (const float*)d_in[1];  // label (B,)
    const float* pm = (const float*)d_in[2];  // prostate_mask
    const float* nm = (const float*)d_in[3];  // needle_mask

    int n  = in_sizes[0];         // B*H*W
    int nb = in_sizes[1];         // B
    int hw = n / nb;              // H*W per batch element
    int n4 = n / 4;
    int hw4 = hw / 4;

    init_acc_kernel<<<1, 1>>>();

    const int threads = 256;
    int blocks = (n4 + threads - 1) / threads;
    if (blocks > 8 * 148) blocks = 8 * 148;   // ~2 vec-iters/thread at this size; grid-stride covers rest

    loss_kernel<<<blocks, threads>>>(
        (const float4*)x, y, (const float4*)pm, (const float4*)nm, n4, hw4);

    finalize_kernel<<<1, 1>>>((float*)d_out);
}